// round 8
// baseline (speedup 1.0000x reference)
#include <cuda_runtime.h>
#include <cuda_bf16.h>

// DynamicUpsamplingFilter: out[b,c,h,w] = sum_{dy,dx} x[b,c,h+dy-1,w+dx-1] * filters[b,dy*3+dx,h,w]
// x [4,128,180,320] f32, filters [4,9,180,320] f32, out [4,128,180,320] f32.
//
// R8: R7's staged unroll-4 float4 structure + R2's shuffle halos.
// Phase 1: 12 independent float4 LDGs (+ 6 predicated 1-lane edge loads on
// lanes 0/31 only). Phase 2: __shfl for interior halos + FMAs. Cuts L1
// wavefronts per warp-channel-iter from ~40 to ~22 while keeping the load
// batching that made R5/R7 fast. Mid-warp row-crossing shuffle garbage is
// neutralized by zero-masked boundary coefficients (proven in R2).

#define B_ 4
#define C_ 128
#define H_ 180
#define W_ 320
#define CPB 16           // channels per block (grid.y = 8)
#define TPB 256
#define U   4            // channel unroll (staged)

__global__ __launch_bounds__(TPB, 2)
void duf_kernel(const float* __restrict__ x,
                const float* __restrict__ filters,
                float* __restrict__ out)
{
    const int HW = H_ * W_;
    int tid = blockIdx.x * TPB + threadIdx.x;
    const int WQ = W_ / 4;             // 80 pixel-quads per row
    int wq = tid % WQ;
    int t2 = tid / WQ;
    int h  = t2 % H_;
    int b  = t2 / H_;
    int w  = wq * 4;
    int lane = threadIdx.x & 31;

    int c0 = blockIdx.y * CPB;

    // ---- 9 filter float4s (tap i, pixels w..w+3) ----
    const float* fb = filters + ((size_t)b * 9) * HW + (size_t)h * W_ + w;
    float4 f[9];
#pragma unroll
    for (int i = 0; i < 9; i++)
        f[i] = __ldg((const float4*)(fb + (size_t)i * HW));

    // ---- boundary masking folded into coefficients ----
    if (h == 0) {
        f[0] = make_float4(0,0,0,0);
        f[1] = make_float4(0,0,0,0);
        f[2] = make_float4(0,0,0,0);
    }
    if (h == H_ - 1) {
        f[6] = make_float4(0,0,0,0);
        f[7] = make_float4(0,0,0,0);
        f[8] = make_float4(0,0,0,0);
    }
    if (w == 0) {                  // pixel0 left taps (also kills row-cross shfl garbage)
        f[0].x = 0.f; f[3].x = 0.f; f[6].x = 0.f;
    }
    if (w + 4 == W_) {             // pixel3 right taps (ditto)
        f[2].w = 0.f; f[5].w = 0.f; f[8].w = 0.f;
    }

    // clamped offsets (clamped values hit zeroed coefficients)
    int hm = (h > 0)      ? h - 1 : 0;
    int hp = (h < H_ - 1) ? h + 1 : h;
    int wl = (w > 0)      ? w - 1 : 0;        // scalar x(w-1)
    int wr = (w + 4 < W_) ? w + 4 : W_ - 1;   // scalar x(w+4)

    const bool ld_l = (lane == 0);    // left halo unavailable via shuffle
    const bool ld_r = (lane == 31);   // right halo unavailable via shuffle

    const float* base = x + ((size_t)(b * C_ + c0)) * HW;
    const float* pm = base + (size_t)hm * W_;
    const float* p0 = base + (size_t)h  * W_;
    const float* pp = base + (size_t)hp * W_;
    float* po = out + (((size_t)(b * C_ + c0)) * H_ + h) * (size_t)W_ + w;

    for (int c = 0; c < CPB; c += U) {
        float4 vm[U], v0[U], vp[U];
        float eml[U], emr[U], ezl[U], ezr[U], epl[U], epr[U];

        // ---- phase 1: independent loads, front-batched ----
#pragma unroll
        for (int u = 0; u < U; u++) {
            const float* qm = pm + (size_t)u * HW;
            const float* q0 = p0 + (size_t)u * HW;
            const float* qp = pp + (size_t)u * HW;
            vm[u] = __ldg((const float4*)(qm + w));
            v0[u] = __ldg((const float4*)(q0 + w));
            vp[u] = __ldg((const float4*)(qp + w));
            // warp-edge lanes only: 1-lane wavefronts
            eml[u] = ld_l ? __ldg(qm + wl) : 0.f;
            ezl[u] = ld_l ? __ldg(q0 + wl) : 0.f;
            epl[u] = ld_l ? __ldg(qp + wl) : 0.f;
            emr[u] = ld_r ? __ldg(qm + wr) : 0.f;
            ezr[u] = ld_r ? __ldg(q0 + wr) : 0.f;
            epr[u] = ld_r ? __ldg(qp + wr) : 0.f;
        }

        // ---- phase 2: shuffles + compute + store ----
#pragma unroll
        for (int u = 0; u < U; u++) {
            float vml = __shfl_up_sync(0xffffffffu,  vm[u].w, 1);
            float v0l = __shfl_up_sync(0xffffffffu,  v0[u].w, 1);
            float vpl = __shfl_up_sync(0xffffffffu,  vp[u].w, 1);
            float vmr = __shfl_down_sync(0xffffffffu, vm[u].x, 1);
            float v0r = __shfl_down_sync(0xffffffffu, v0[u].x, 1);
            float vpr = __shfl_down_sync(0xffffffffu, vp[u].x, 1);
            if (ld_l) { vml = eml[u]; v0l = ezl[u]; vpl = epl[u]; }
            if (ld_r) { vmr = emr[u]; v0r = ezr[u]; vpr = epr[u]; }

            float4 acc;
            acc.x = f[0].x*vml      + f[1].x*vm[u].x + f[2].x*vm[u].y
                  + f[3].x*v0l      + f[4].x*v0[u].x + f[5].x*v0[u].y
                  + f[6].x*vpl      + f[7].x*vp[u].x + f[8].x*vp[u].y;
            acc.y = f[0].y*vm[u].x + f[1].y*vm[u].y + f[2].y*vm[u].z
                  + f[3].y*v0[u].x + f[4].y*v0[u].y + f[5].y*v0[u].z
                  + f[6].y*vp[u].x + f[7].y*vp[u].y + f[8].y*vp[u].z;
            acc.z = f[0].z*vm[u].y + f[1].z*vm[u].z + f[2].z*vm[u].w
                  + f[3].z*v0[u].y + f[4].z*v0[u].z + f[5].z*v0[u].w
                  + f[6].z*vp[u].y + f[7].z*vp[u].z + f[8].z*vp[u].w;
            acc.w = f[0].w*vm[u].z + f[1].w*vm[u].w + f[2].w*vmr
                  + f[3].w*v0[u].z + f[4].w*v0[u].w + f[5].w*v0r
                  + f[6].w*vp[u].z + f[7].w*vp[u].w + f[8].w*vpr;

            *((float4*)(po + (size_t)u * HW)) = acc;
        }

        pm += (size_t)U * HW;
        p0 += (size_t)U * HW;
        pp += (size_t)U * HW;
        po += (size_t)U * HW;
    }
}

extern "C" void kernel_launch(void* const* d_in, const int* in_sizes, int n_in,
                              void* d_out, int out_size)
{
    const float* x       = (const float*)d_in[0];
    const float* filters = (const float*)d_in[1];
    float* out           = (float*)d_out;

    int spatial_threads = B_ * H_ * (W_ / 4);     // 57600
    dim3 grid(spatial_threads / TPB, C_ / CPB);   // (225, 8) = 1800 blocks
    duf_kernel<<<grid, TPB>>>(x, filters, out);
}

// round 9
// speedup vs baseline: 1.0508x; 1.0508x over previous
#include <cuda_runtime.h>
#include <cuda_bf16.h>

// DynamicUpsamplingFilter: out[b,c,h,w] = sum_{dy,dx} x[b,c,h+dy-1,w+dx-1] * filters[b,dy*3+dx,h,w]
// x [4,128,180,320] f32, filters [4,9,180,320] f32, out [4,128,180,320] f32.
//
// R9: software-pipelined double buffer over channels. While computing batch i
// (2 channels), batch i+1's 6 float4 loads (24 x 128B lines/warp) are already
// in flight -> load duty cycle ~100% instead of ~50% (the staged R7/R8 loops
// had zero loads outstanding during their compute phase, pinning DRAM at 53%).
// Halos via shuffles + predicated lane-0/31 edge loads (R8, keeps L1 low).
// Boundary handling hoisted into zeroed coefficients + clamped offsets.

#define B_ 4
#define C_ 128
#define H_ 180
#define W_ 320
#define CPB 16           // channels per block (grid.y = 8)
#define TPB 256
#define U   2            // channels per pipeline batch; NB = CPB/U = 8 batches

__global__ __launch_bounds__(TPB, 2)
void duf_kernel(const float* __restrict__ x,
                const float* __restrict__ filters,
                float* __restrict__ out)
{
    const int HW = H_ * W_;
    int tid = blockIdx.x * TPB + threadIdx.x;
    const int WQ = W_ / 4;             // 80 pixel-quads per row
    int wq = tid % WQ;
    int t2 = tid / WQ;
    int h  = t2 % H_;
    int b  = t2 / H_;
    int w  = wq * 4;
    int lane = threadIdx.x & 31;

    int c0 = blockIdx.y * CPB;

    // ---- 9 filter float4s (tap i, pixels w..w+3) ----
    const float* fb = filters + ((size_t)b * 9) * HW + (size_t)h * W_ + w;
    float4 f[9];
#pragma unroll
    for (int i = 0; i < 9; i++)
        f[i] = __ldg((const float4*)(fb + (size_t)i * HW));

    // ---- boundary masks folded into coefficients ----
    if (h == 0) {
        f[0] = make_float4(0,0,0,0);
        f[1] = make_float4(0,0,0,0);
        f[2] = make_float4(0,0,0,0);
    }
    if (h == H_ - 1) {
        f[6] = make_float4(0,0,0,0);
        f[7] = make_float4(0,0,0,0);
        f[8] = make_float4(0,0,0,0);
    }
    if (w == 0) {                  // pixel0 left taps (also kills row-cross shfl garbage)
        f[0].x = 0.f; f[3].x = 0.f; f[6].x = 0.f;
    }
    if (w + 4 == W_) {             // pixel3 right taps (ditto)
        f[2].w = 0.f; f[5].w = 0.f; f[8].w = 0.f;
    }

    // clamped offsets (clamped values hit zeroed coefficients)
    int hm = (h > 0)      ? h - 1 : 0;
    int hp = (h < H_ - 1) ? h + 1 : h;
    int wl = (w > 0)      ? w - 1 : 0;        // scalar x(w-1)
    int wr = (w + 4 < W_) ? w + 4 : W_ - 1;   // scalar x(w+4)

    const bool ld_l = (lane == 0);
    const bool ld_r = (lane == 31);

    const float* base = x + ((size_t)(b * C_ + c0)) * HW;
    const float* pm = base + (size_t)hm * W_;   // load-side pointers (advanced by LOADB)
    const float* p0 = base + (size_t)h  * W_;
    const float* pp = base + (size_t)hp * W_;
    float* po = out + (((size_t)(b * C_ + c0)) * H_ + h) * (size_t)W_ + w;  // store side

    // double-buffered registers
    float4 Avm[U], Av0[U], Avp[U], Bvm[U], Bv0[U], Bvp[U];
    float  Aeml[U], Aezl[U], Aepl[U], Aemr[U], Aezr[U], Aepr[U];
    float  Beml[U], Bezl[U], Bepl[U], Bemr[U], Bezr[U], Bepr[U];

#define LOADB(P)                                                        \
    {                                                                   \
        _Pragma("unroll")                                               \
        for (int u = 0; u < U; u++) {                                   \
            const float* qm = pm + (size_t)u * HW;                      \
            const float* q0 = p0 + (size_t)u * HW;                      \
            const float* qp = pp + (size_t)u * HW;                      \
            P##vm[u] = __ldg((const float4*)(qm + w));                  \
            P##v0[u] = __ldg((const float4*)(q0 + w));                  \
            P##vp[u] = __ldg((const float4*)(qp + w));                  \
            P##eml[u] = ld_l ? __ldg(qm + wl) : 0.f;                    \
            P##ezl[u] = ld_l ? __ldg(q0 + wl) : 0.f;                    \
            P##epl[u] = ld_l ? __ldg(qp + wl) : 0.f;                    \
            P##emr[u] = ld_r ? __ldg(qm + wr) : 0.f;                    \
            P##ezr[u] = ld_r ? __ldg(q0 + wr) : 0.f;                    \
            P##epr[u] = ld_r ? __ldg(qp + wr) : 0.f;                    \
        }                                                               \
        pm += (size_t)U * HW; p0 += (size_t)U * HW; pp += (size_t)U * HW; \
    }

#define COMPUTEB(P)                                                     \
    {                                                                   \
        _Pragma("unroll")                                               \
        for (int u = 0; u < U; u++) {                                   \
            float vml = __shfl_up_sync(0xffffffffu,  P##vm[u].w, 1);    \
            float v0l = __shfl_up_sync(0xffffffffu,  P##v0[u].w, 1);    \
            float vpl = __shfl_up_sync(0xffffffffu,  P##vp[u].w, 1);    \
            float vmr = __shfl_down_sync(0xffffffffu, P##vm[u].x, 1);   \
            float v0r = __shfl_down_sync(0xffffffffu, P##v0[u].x, 1);   \
            float vpr = __shfl_down_sync(0xffffffffu, P##vp[u].x, 1);   \
            if (ld_l) { vml = P##eml[u]; v0l = P##ezl[u]; vpl = P##epl[u]; } \
            if (ld_r) { vmr = P##emr[u]; v0r = P##ezr[u]; vpr = P##epr[u]; } \
            float4 acc;                                                 \
            acc.x = f[0].x*vml        + f[1].x*P##vm[u].x + f[2].x*P##vm[u].y \
                  + f[3].x*v0l        + f[4].x*P##v0[u].x + f[5].x*P##v0[u].y \
                  + f[6].x*vpl        + f[7].x*P##vp[u].x + f[8].x*P##vp[u].y; \
            acc.y = f[0].y*P##vm[u].x + f[1].y*P##vm[u].y + f[2].y*P##vm[u].z \
                  + f[3].y*P##v0[u].x + f[4].y*P##v0[u].y + f[5].y*P##v0[u].z \
                  + f[6].y*P##vp[u].x + f[7].y*P##vp[u].y + f[8].y*P##vp[u].z; \
            acc.z = f[0].z*P##vm[u].y + f[1].z*P##vm[u].z + f[2].z*P##vm[u].w \
                  + f[3].z*P##v0[u].y + f[4].z*P##v0[u].z + f[5].z*P##v0[u].w \
                  + f[6].z*P##vp[u].y + f[7].z*P##vp[u].z + f[8].z*P##vp[u].w; \
            acc.w = f[0].w*P##vm[u].z + f[1].w*P##vm[u].w + f[2].w*vmr   \
                  + f[3].w*P##v0[u].z + f[4].w*P##v0[u].w + f[5].w*v0r   \
                  + f[6].w*P##vp[u].z + f[7].w*P##vp[u].w + f[8].w*vpr;  \
            *((float4*)(po + (size_t)u * HW)) = acc;                    \
        }                                                               \
        po += (size_t)U * HW;                                           \
    }

    // ---- 2-deep pipeline over NB = CPB/U = 8 batches ----
    LOADB(A);                       // batch 0
#pragma unroll
    for (int cb = 0; cb < CPB / U - 2; cb += 2) {
        LOADB(B);                   // batch cb+1 in flight while computing cb
        COMPUTEB(A);
        LOADB(A);                   // batch cb+2 in flight while computing cb+1
        COMPUTEB(B);
    }
    LOADB(B);                       // last batch
    COMPUTEB(A);
    COMPUTEB(B);

#undef LOADB
#undef COMPUTEB
}

extern "C" void kernel_launch(void* const* d_in, const int* in_sizes, int n_in,
                              void* d_out, int out_size)
{
    const float* x       = (const float*)d_in[0];
    const float* filters = (const float*)d_in[1];
    float* out           = (float*)d_out;

    int spatial_threads = B_ * H_ * (W_ / 4);     // 57600
    dim3 grid(spatial_threads / TPB, C_ / CPB);   // (225, 8) = 1800 blocks
    duf_kernel<<<grid, TPB>>>(x, filters, out);
}

// round 10
// speedup vs baseline: 1.0935x; 1.0406x over previous
#include <cuda_runtime.h>
#include <cuda_bf16.h>

// DynamicUpsamplingFilter: out[b,c,h,w] = sum_{dy,dx} x[b,c,h+dy-1,w+dx-1] * filters[b,dy*3+dx,h,w]
// x [4,128,180,320] f32, filters [4,9,180,320] f32, out [4,128,180,320] f32.
//
// R10: R9's double-buffered channel pipeline with register pressure fixed.
// - Packed edge values: one scalar per row per channel serves BOTH lane 0
//   (left halo) and lane 31 (right halo); selected vs shuffle at consume
//   time. Halves edge registers and edge loads.
// - CPB=32 halves per-block prologue overhead (filter fetch latency).
// - Pipeline loop kept rolled (unroll 1) for small I$ footprint.
// Target: regs ~114 so ptxas preserves the load-ahead schedule instead of
// serializing to fit the 128-reg / 2-CTA cap (R9 was pinned at 128).

#define B_ 4
#define C_ 128
#define H_ 180
#define W_ 320
#define CPB 32           // channels per block (grid.y = 4)
#define TPB 256
#define U   2            // channels per pipeline batch; 16 batches

__global__ __launch_bounds__(TPB, 2)
void duf_kernel(const float* __restrict__ x,
                const float* __restrict__ filters,
                float* __restrict__ out)
{
    const int HW = H_ * W_;
    int tid = blockIdx.x * TPB + threadIdx.x;
    const int WQ = W_ / 4;             // 80 pixel-quads per row
    int wq = tid % WQ;
    int t2 = tid / WQ;
    int h  = t2 % H_;
    int b  = t2 / H_;
    int w  = wq * 4;
    int lane = threadIdx.x & 31;

    int c0 = blockIdx.y * CPB;

    // ---- 9 filter float4s (tap i, pixels w..w+3) ----
    const float* fb = filters + ((size_t)b * 9) * HW + (size_t)h * W_ + w;
    float4 f[9];
#pragma unroll
    for (int i = 0; i < 9; i++)
        f[i] = __ldg((const float4*)(fb + (size_t)i * HW));

    // ---- boundary masks folded into coefficients ----
    if (h == 0) {
        f[0] = make_float4(0,0,0,0);
        f[1] = make_float4(0,0,0,0);
        f[2] = make_float4(0,0,0,0);
    }
    if (h == H_ - 1) {
        f[6] = make_float4(0,0,0,0);
        f[7] = make_float4(0,0,0,0);
        f[8] = make_float4(0,0,0,0);
    }
    if (w == 0) {                  // pixel0 left taps (also kills row-cross shfl garbage)
        f[0].x = 0.f; f[3].x = 0.f; f[6].x = 0.f;
    }
    if (w + 4 == W_) {             // pixel3 right taps (ditto)
        f[2].w = 0.f; f[5].w = 0.f; f[8].w = 0.f;
    }

    // clamped offsets (clamped values hit zeroed coefficients)
    int hm = (h > 0)      ? h - 1 : 0;
    int hp = (h < H_ - 1) ? h + 1 : h;
    int wl = (w > 0)      ? w - 1 : 0;        // scalar x(w-1)
    int wr = (w + 4 < W_) ? w + 4 : W_ - 1;   // scalar x(w+4)

    const bool ld_l = (lane == 0);
    const bool ld_r = (lane == 31);
    const bool ld_e = ld_l | ld_r;            // this lane loads ONE edge value
    const int  eoff = ld_l ? wl : wr;         // which one

    const float* base = x + ((size_t)(b * C_ + c0)) * HW;
    const float* pm = base + (size_t)hm * W_;   // load-side pointers
    const float* p0 = base + (size_t)h  * W_;
    const float* pp = base + (size_t)hp * W_;
    float* po = out + (((size_t)(b * C_ + c0)) * H_ + h) * (size_t)W_ + w;

    // double-buffered registers: 6 float4 + 6 packed-edge scalars per buffer
    float4 Avm[U], Av0[U], Avp[U], Bvm[U], Bv0[U], Bvp[U];
    float  Aem[U], Ae0[U], Aep[U], Bem[U], Be0[U], Bep[U];

#define LOADB(P)                                                        \
    {                                                                   \
        _Pragma("unroll")                                               \
        for (int u = 0; u < U; u++) {                                   \
            const float* qm = pm + (size_t)u * HW;                      \
            const float* q0 = p0 + (size_t)u * HW;                      \
            const float* qp = pp + (size_t)u * HW;                      \
            P##vm[u] = __ldg((const float4*)(qm + w));                  \
            P##v0[u] = __ldg((const float4*)(q0 + w));                  \
            P##vp[u] = __ldg((const float4*)(qp + w));                  \
            P##em[u] = ld_e ? __ldg(qm + eoff) : 0.f;                   \
            P##e0[u] = ld_e ? __ldg(q0 + eoff) : 0.f;                   \
            P##ep[u] = ld_e ? __ldg(qp + eoff) : 0.f;                   \
        }                                                               \
        pm += (size_t)U * HW; p0 += (size_t)U * HW; pp += (size_t)U * HW; \
    }

#define COMPUTEB(P)                                                     \
    {                                                                   \
        _Pragma("unroll")                                               \
        for (int u = 0; u < U; u++) {                                   \
            float sml = __shfl_up_sync(0xffffffffu,  P##vm[u].w, 1);    \
            float s0l = __shfl_up_sync(0xffffffffu,  P##v0[u].w, 1);    \
            float spl = __shfl_up_sync(0xffffffffu,  P##vp[u].w, 1);    \
            float smr = __shfl_down_sync(0xffffffffu, P##vm[u].x, 1);   \
            float s0r = __shfl_down_sync(0xffffffffu, P##v0[u].x, 1);   \
            float spr = __shfl_down_sync(0xffffffffu, P##vp[u].x, 1);   \
            float vml = ld_l ? P##em[u] : sml;                          \
            float v0l = ld_l ? P##e0[u] : s0l;                          \
            float vpl = ld_l ? P##ep[u] : spl;                          \
            float vmr = ld_r ? P##em[u] : smr;                          \
            float v0r = ld_r ? P##e0[u] : s0r;                          \
            float vpr = ld_r ? P##ep[u] : spr;                          \
            float4 acc;                                                 \
            acc.x = f[0].x*vml        + f[1].x*P##vm[u].x + f[2].x*P##vm[u].y \
                  + f[3].x*v0l        + f[4].x*P##v0[u].x + f[5].x*P##v0[u].y \
                  + f[6].x*vpl        + f[7].x*P##vp[u].x + f[8].x*P##vp[u].y; \
            acc.y = f[0].y*P##vm[u].x + f[1].y*P##vm[u].y + f[2].y*P##vm[u].z \
                  + f[3].y*P##v0[u].x + f[4].y*P##v0[u].y + f[5].y*P##v0[u].z \
                  + f[6].y*P##vp[u].x + f[7].y*P##vp[u].y + f[8].y*P##vp[u].z; \
            acc.z = f[0].z*P##vm[u].y + f[1].z*P##vm[u].z + f[2].z*P##vm[u].w \
                  + f[3].z*P##v0[u].y + f[4].z*P##v0[u].z + f[5].z*P##v0[u].w \
                  + f[6].z*P##vp[u].y + f[7].z*P##vp[u].z + f[8].z*P##vp[u].w; \
            acc.w = f[0].w*P##vm[u].z + f[1].w*P##vm[u].w + f[2].w*vmr   \
                  + f[3].w*P##v0[u].z + f[4].w*P##v0[u].w + f[5].w*v0r   \
                  + f[6].w*P##vp[u].z + f[7].w*P##vp[u].w + f[8].w*vpr;  \
            *((float4*)(po + (size_t)u * HW)) = acc;                    \
        }                                                               \
        po += (size_t)U * HW;                                           \
    }

    // ---- 2-deep pipeline over CPB/U = 16 batches ----
    LOADB(A);
#pragma unroll 1
    for (int cb = 0; cb < CPB / U - 2; cb += 2) {
        LOADB(B);                   // next batch in flight while computing current
        COMPUTEB(A);
        LOADB(A);
        COMPUTEB(B);
    }
    LOADB(B);
    COMPUTEB(A);
    COMPUTEB(B);

#undef LOADB
#undef COMPUTEB
}

extern "C" void kernel_launch(void* const* d_in, const int* in_sizes, int n_in,
                              void* d_out, int out_size)
{
    const float* x       = (const float*)d_in[0];
    const float* filters = (const float*)d_in[1];
    float* out           = (float*)d_out;

    int spatial_threads = B_ * H_ * (W_ / 4);     // 57600
    dim3 grid(spatial_threads / TPB, C_ / CPB);   // (225, 4) = 900 blocks
    duf_kernel<<<grid, TPB>>>(x, filters, out);
}